// round 7
// baseline (speedup 1.0000x reference)
#include <cuda_runtime.h>
#include <cstddef>

#define N_NODES 50000
#define N_EDGES 800000
#define NUM_GRAPHS 256
#define IN_DIM 128
#define HDIM 64
#define HID 256
#define EPS_BN 1e-5f
#define SCAN_BLOCKS ((N_NODES + 1023) / 1024)

// ---------------- device scratch (no allocation allowed) ----------------
__device__ __align__(256) int   g_deg[N_NODES];
__device__ __align__(256) int   g_row_start[N_NODES + 1];
__device__ __align__(256) int   g_cursor[N_NODES];
__device__ __align__(256) int   g_csr[N_EDGES];
__device__ __align__(256) int   g_blocksum[64];
__device__ __align__(256) float g_xl[N_NODES * HDIM];
__device__ __align__(256) float g_xr[N_NODES * HDIM];
__device__ __align__(256) float g_hA[N_NODES * HDIM];
__device__ __align__(256) float g_hB[N_NODES * HDIM];
__device__ __align__(256) float g_pooled[NUM_GRAPHS * HDIM];
__device__ __align__(256) float g_c1[NUM_GRAPHS * HID];
__device__ __align__(256) float g_c2[NUM_GRAPHS * (HID / 2)];
__device__ __align__(256) float g_c3[NUM_GRAPHS * (HID / 4)];
__device__ int g_ei64;   // 1 if edge_index is int64, 0 if int32
__device__ int g_b64;    // same for batch

// ---------------- f32x2 packed math (FFMA2 — exact fp32, 2 MACs/issue) ----
__device__ __forceinline__ unsigned long long fma2(unsigned long long a,
                                                   unsigned long long b,
                                                   unsigned long long c) {
    unsigned long long d;
    asm("fma.rn.f32x2 %0, %1, %2, %3;" : "=l"(d) : "l"(a), "l"(b), "l"(c));
    return d;
}
__device__ __forceinline__ unsigned long long pack2(float x) {
    unsigned long long d;
    asm("mov.b64 %0, {%1, %1};" : "=l"(d) : "f"(x));
    return d;
}
__device__ __forceinline__ float2 unpack2(unsigned long long v) {
    float2 r;
    asm("mov.b64 {%0, %1}, %2;" : "=f"(r.x), "=f"(r.y) : "l"(v));
    return r;
}

__device__ __forceinline__ int idx_at(const void* p, long long i, int is64) {
    return is64 ? (int)((const long long*)p)[i] : ((const int*)p)[i];
}

// ---------------- zero + dtype detect (fused) ----------------
__global__ void zero_detect_kernel(const void* ei, const void* batch) {
    int t = blockIdx.x * blockDim.x + threadIdx.x;
    if (t < N_NODES) { g_deg[t] = 0; g_cursor[t] = 0; }
    if (t == 0) {
        const int* p = (const int*)ei;
        int is64 = 1;
        for (int i = 0; i < 64; i++)
            if (p[2 * i + 1] != 0) { is64 = 0; break; }
        g_ei64 = is64;
        // batch probes at midpoint: int64-candidate idx [12500,12564) reads
        // int32 slots < 25128 < 50000 -> in-bounds either way; sorted values
        // there are ~64-128 (nonzero).
        const int* pb = (const int*)batch;
        int b64 = 1;
        for (int i = 12500; i < 12564; i++)
            if (pb[2 * i + 1] != 0) { b64 = 0; break; }
        g_b64 = b64;
    }
}

__global__ void count_deg_kernel(const void* ei) {
    int e = blockIdx.x * blockDim.x + threadIdx.x;
    if (e >= N_EDGES) return;
    int is64 = g_ei64;
    int dst = idx_at(ei, (long long)N_EDGES + e, is64);
    atomicAdd(&g_deg[dst], 1);
}

// --- parallel scan ---
__global__ void scanA_kernel() {
    __shared__ int s[1024];
    int tid = threadIdx.x;
    int idx = blockIdx.x * 1024 + tid;
    int v = (idx < N_NODES) ? g_deg[idx] : 0;
    s[tid] = v;
    __syncthreads();
#pragma unroll
    for (int off = 1; off < 1024; off <<= 1) {
        int t = (tid >= off) ? s[tid - off] : 0;
        __syncthreads();
        s[tid] += t;
        __syncthreads();
    }
    if (idx < N_NODES) g_row_start[idx + 1] = s[tid];
    if (tid == 1023) g_blocksum[blockIdx.x] = s[1023];
}

__global__ void scanB_kernel() {
    __shared__ int s[64];
    int tid = threadIdx.x;   // 64 threads
    int v = (tid < SCAN_BLOCKS) ? g_blocksum[tid] : 0;
    s[tid] = v;
    __syncthreads();
#pragma unroll
    for (int off = 1; off < 64; off <<= 1) {
        int t = (tid >= off) ? s[tid - off] : 0;
        __syncthreads();
        s[tid] += t;
        __syncthreads();
    }
    if (tid < SCAN_BLOCKS) g_blocksum[tid] = (tid > 0) ? s[tid - 1] : 0;
}

__global__ void scanC_kernel() {
    int idx = blockIdx.x * blockDim.x + threadIdx.x;
    if (idx < N_NODES) g_row_start[idx + 1] += g_blocksum[idx >> 10];
    if (idx == 0) g_row_start[0] = 0;
}

__global__ void fill_csr_kernel(const void* ei) {
    int e = blockIdx.x * blockDim.x + threadIdx.x;
    if (e >= N_EDGES) return;
    int is64 = g_ei64;
    int src = idx_at(ei, e, is64);
    int dst = idx_at(ei, (long long)N_EDGES + e, is64);
    int pos = atomicAdd(&g_cursor[dst], 1);
    g_csr[g_row_start[dst] + pos] = src;
}

// ---------------- dual GEMM via FFMA2: (xl, xr) = h @ (Wl, Wr) ----------
// tile: 128 nodes x 128 cols per 256-thread block; thread: 4 nodes x 8 pairs.
template <int K>
__global__ __launch_bounds__(256)
void gemm_dual_kernel(const float* __restrict__ h,
                      const float* __restrict__ Wl, const float* __restrict__ Wr,
                      float* __restrict__ xl, float* __restrict__ xr) {
    __shared__ float Hs[128 * 36];    // 128 nodes x 32 k, stride 36
    __shared__ float Ws[32 * 128];    // 32 k x 128 cols [Wl | Wr]

    int nb = blockIdx.x * 128;
    int tid = threadIdx.x;
    int colg  = tid & 7;     // 8 groups x 16 cols
    int nodeg = tid >> 3;    // 32 groups x 4 nodes

    unsigned long long acc[4][8];
#pragma unroll
    for (int i = 0; i < 4; i++)
#pragma unroll
        for (int p = 0; p < 8; p++) acc[i][p] = 0ull;

    for (int k0 = 0; k0 < K; k0 += 32) {
        // load h tile: 128 nodes x 32 k = 1024 float4
#pragma unroll
        for (int q = tid; q < 1024; q += 256) {
            int n = q >> 3;
            int kq = q & 7;
            int gn = nb + n;
            float4 v = make_float4(0.f, 0.f, 0.f, 0.f);
            if (gn < N_NODES)
                v = *(const float4*)&h[(size_t)gn * K + k0 + kq * 4];
            *(float4*)&Hs[n * 36 + kq * 4] = v;
        }
        // load weights: 32 k x 128 cols = 1024 float4
#pragma unroll
        for (int q = tid; q < 1024; q += 256) {
            int k = q >> 5;
            int j4 = q & 31;
            float4 w;
            if (j4 < 16)
                w = *(const float4*)&Wl[(size_t)(k0 + k) * 64 + j4 * 4];
            else
                w = *(const float4*)&Wr[(size_t)(k0 + k) * 64 + (j4 - 16) * 4];
            *(float4*)&Ws[k * 128 + j4 * 4] = w;
        }
        __syncthreads();

#pragma unroll
        for (int kk = 0; kk < 32; kk++) {
            const ulonglong2* wp = (const ulonglong2*)(Ws + kk * 128 + colg * 16);
            ulonglong2 wv0 = wp[0];
            ulonglong2 wv1 = wp[1];
            ulonglong2 wv2 = wp[2];
            ulonglong2 wv3 = wp[3];
#pragma unroll
            for (int i = 0; i < 4; i++) {
                unsigned long long a2 = pack2(Hs[(nodeg * 4 + i) * 36 + kk]);
                acc[i][0] = fma2(a2, wv0.x, acc[i][0]);
                acc[i][1] = fma2(a2, wv0.y, acc[i][1]);
                acc[i][2] = fma2(a2, wv1.x, acc[i][2]);
                acc[i][3] = fma2(a2, wv1.y, acc[i][3]);
                acc[i][4] = fma2(a2, wv2.x, acc[i][4]);
                acc[i][5] = fma2(a2, wv2.y, acc[i][5]);
                acc[i][6] = fma2(a2, wv3.x, acc[i][6]);
                acc[i][7] = fma2(a2, wv3.y, acc[i][7]);
            }
        }
        __syncthreads();
    }

#pragma unroll
    for (int i = 0; i < 4; i++) {
        int gn = nb + nodeg * 4 + i;
        if (gn < N_NODES) {
            float* base = (colg < 4) ? &xl[(size_t)gn * 64 + colg * 16]
                                     : &xr[(size_t)gn * 64 + (colg - 4) * 16];
#pragma unroll
            for (int q = 0; q < 4; q++) {
                float2 p0 = unpack2(acc[i][q * 2]);
                float2 p1 = unpack2(acc[i][q * 2 + 1]);
                float4 o = make_float4(p0.x, p0.y, p1.x, p1.y);
                *(float4*)(base + q * 4) = o;
            }
        }
    }
}

// ---------------- fused aggregate + combine (warp per node) ----------------
// out[n] = mean_{src in N(n)} xl[src] + bl + xr[n]; each edge = one 256B read,
// trip count warp-uniform -> zero divergence.
__global__ void aggregate_combine_kernel(const float* __restrict__ xl,
                                         const float* __restrict__ xr,
                                         const float* __restrict__ bl,
                                         float* __restrict__ out) {
    int w = (blockIdx.x * blockDim.x + threadIdx.x) >> 5;
    if (w >= N_NODES) return;
    int lane = threadIdx.x & 31;
    int s = g_row_start[w];
    int e = g_row_start[w + 1];
    const float2* xl2 = (const float2*)xl;

    float2 a0 = make_float2(0.f, 0.f);
    float2 a1 = make_float2(0.f, 0.f);
    float2 a2 = make_float2(0.f, 0.f);
    float2 a3 = make_float2(0.f, 0.f);
    int i = s;
    for (; i + 4 <= e; i += 4) {
        int s0 = __ldg(&g_csr[i]);
        int s1 = __ldg(&g_csr[i + 1]);
        int s2 = __ldg(&g_csr[i + 2]);
        int s3 = __ldg(&g_csr[i + 3]);
        float2 v0 = __ldg(&xl2[(size_t)s0 * 32 + lane]);
        float2 v1 = __ldg(&xl2[(size_t)s1 * 32 + lane]);
        float2 v2 = __ldg(&xl2[(size_t)s2 * 32 + lane]);
        float2 v3 = __ldg(&xl2[(size_t)s3 * 32 + lane]);
        a0.x += v0.x; a0.y += v0.y;
        a1.x += v1.x; a1.y += v1.y;
        a2.x += v2.x; a2.y += v2.y;
        a3.x += v3.x; a3.y += v3.y;
    }
    for (; i < e; i++) {
        int s0 = __ldg(&g_csr[i]);
        float2 v0 = __ldg(&xl2[(size_t)s0 * 32 + lane]);
        a0.x += v0.x; a0.y += v0.y;
    }
    float sx = (a0.x + a1.x) + (a2.x + a3.x);
    float sy = (a0.y + a1.y) + (a2.y + a3.y);
    float inv = 1.0f / fmaxf((float)(e - s), 1.0f);
    float2 b = __ldg(&((const float2*)bl)[lane]);
    float2 r = __ldg(&((const float2*)xr)[(size_t)w * 32 + lane]);
    float2 o;
    o.x = sx * inv + b.x + r.x;
    o.y = sy * inv + b.y + r.y;
    ((float2*)out)[(size_t)w * 32 + lane] = o;
}

// ---------------- pool with inlined graph bounds (batch sorted) ----------
__global__ void pool_kernel(const float* __restrict__ h, const void* __restrict__ batch) {
    int g = blockIdx.x;
    __shared__ int sse[2];
    if (threadIdx.x < 2) {
        int target = g + threadIdx.x;
        int b64 = g_b64;
        int lo = 0, hi = N_NODES;
        while (lo < hi) {
            int mid = (lo + hi) >> 1;
            if (idx_at(batch, mid, b64) < target) lo = mid + 1; else hi = mid;
        }
        sse[threadIdx.x] = lo;
    }
    __syncthreads();
    int s = sse[0], e = sse[1];
    int f = threadIdx.x;   // 64 threads
    float acc = 0.0f;
    for (int i = s; i < e; i++)
        acc += h[(size_t)i * HDIM + f];
    g_pooled[g * HDIM + f] = acc / fmaxf((float)(e - s), 1.0f);
}

// ---------------- fused lin + BN(training) + tanh ----------------
__device__ __forceinline__ float blkred256(float v) {
    __shared__ float sh[256];
    int tid = threadIdx.x;
    sh[tid] = v;
    __syncthreads();
    for (int o = 128; o > 0; o >>= 1) {
        if (tid < o) sh[tid] += sh[tid + o];
        __syncthreads();
    }
    float r = sh[0];
    __syncthreads();
    return r;
}

// grid = Jdim blocks, block = 256 threads (one per graph row)
template <int K>
__global__ void lin_bn_tanh_kernel(const float* __restrict__ in, const float* __restrict__ W,
                                   const float* __restrict__ bias,
                                   const float* __restrict__ gamma, const float* __restrict__ beta,
                                   float* __restrict__ out, int J) {
    int j = blockIdx.x;
    int g = threadIdx.x;
    float acc = __ldg(&bias[j]);
#pragma unroll 8
    for (int k = 0; k < K; k++)
        acc = fmaf(__ldg(&in[g * K + k]), __ldg(&W[k * J + j]), acc);
    float s = blkred256(acc);
    __shared__ float mean_s, inv_s;
    if (g == 0) mean_s = s * (1.0f / NUM_GRAPHS);
    __syncthreads();
    float d = acc - mean_s;
    float s2 = blkred256(d * d);
    if (g == 0) inv_s = rsqrtf(s2 * (1.0f / NUM_GRAPHS) + EPS_BN);
    __syncthreads();
    out[g * J + j] = tanhf(d * inv_s * __ldg(&gamma[j]) + __ldg(&beta[j]));
}

// final linear (no BN): grid = 10 blocks, block = 256
__global__ void lin_final_kernel(const float* __restrict__ in, const float* __restrict__ W,
                                 const float* __restrict__ b, float* __restrict__ out) {
    int j = blockIdx.x;
    int g = threadIdx.x;
    float acc = __ldg(&b[j]);
#pragma unroll
    for (int k = 0; k < HID / 4; k++)
        acc = fmaf(__ldg(&in[g * (HID / 4) + k]), __ldg(&W[k * 10 + j]), acc);
    out[g * 10 + j] = acc;
}

// ---------------- launcher ----------------
extern "C" void kernel_launch(void* const* d_in, const int* in_sizes, int n_in,
                              void* d_out, int out_size) {
    const float* x       = (const float*)d_in[0];
    const void*  ei      = d_in[1];
    const void*  batch   = d_in[2];
    const float* W1l     = (const float*)d_in[3];
    const float* b1l     = (const float*)d_in[4];
    const float* W1r     = (const float*)d_in[5];
    const float* W2l     = (const float*)d_in[6];
    const float* b2l     = (const float*)d_in[7];
    const float* W2r     = (const float*)d_in[8];
    const float* W3l     = (const float*)d_in[9];
    const float* b3l     = (const float*)d_in[10];
    const float* W3r     = (const float*)d_in[11];
    const float* lin1_w  = (const float*)d_in[12];
    const float* lin1_b  = (const float*)d_in[13];
    const float* g1      = (const float*)d_in[14];
    const float* be1     = (const float*)d_in[15];
    const float* lin2_w  = (const float*)d_in[16];
    const float* lin2_b  = (const float*)d_in[17];
    const float* g2      = (const float*)d_in[18];
    const float* be2     = (const float*)d_in[19];
    const float* lin3_w  = (const float*)d_in[20];
    const float* lin3_b  = (const float*)d_in[21];
    const float* g3      = (const float*)d_in[22];
    const float* be3     = (const float*)d_in[23];
    const float* lin4_w  = (const float*)d_in[24];
    const float* lin4_b  = (const float*)d_in[25];
    float* out = (float*)d_out;

    float *xl, *xr, *hA, *hB, *pooled, *c1, *c2, *c3;
    cudaGetSymbolAddress((void**)&xl,     g_xl);
    cudaGetSymbolAddress((void**)&xr,     g_xr);
    cudaGetSymbolAddress((void**)&hA,     g_hA);
    cudaGetSymbolAddress((void**)&hB,     g_hB);
    cudaGetSymbolAddress((void**)&pooled, g_pooled);
    cudaGetSymbolAddress((void**)&c1,     g_c1);
    cudaGetSymbolAddress((void**)&c2,     g_c2);
    cudaGetSymbolAddress((void**)&c3,     g_c3);

    const int NTILE = (N_NODES + 127) / 128;
    const int AGG_BLOCKS = (N_NODES * 32 + 255) / 256;   // warp per node

    zero_detect_kernel<<<(N_NODES + 255) / 256, 256>>>(ei, batch);
    count_deg_kernel<<<(N_EDGES + 255) / 256, 256>>>(ei);
    scanA_kernel<<<SCAN_BLOCKS, 1024>>>();
    scanB_kernel<<<1, 64>>>();
    scanC_kernel<<<(N_NODES + 255) / 256, 256>>>();
    fill_csr_kernel<<<(N_EDGES + 255) / 256, 256>>>(ei);

    // layer 1 (project first, then aggregate at width 64)
    gemm_dual_kernel<IN_DIM><<<NTILE, 256>>>(x, W1l, W1r, xl, xr);
    aggregate_combine_kernel<<<AGG_BLOCKS, 256>>>(xl, xr, b1l, hA);

    // layer 2
    gemm_dual_kernel<HDIM><<<NTILE, 256>>>(hA, W2l, W2r, xl, xr);
    aggregate_combine_kernel<<<AGG_BLOCKS, 256>>>(xl, xr, b2l, hB);

    // layer 3
    gemm_dual_kernel<HDIM><<<NTILE, 256>>>(hB, W3l, W3r, xl, xr);
    aggregate_combine_kernel<<<AGG_BLOCKS, 256>>>(xl, xr, b3l, hA);

    // global mean pool (bounds inlined)
    pool_kernel<<<NUM_GRAPHS, HDIM>>>(hA, batch);

    // MLP head (fused lin+BN+tanh)
    lin_bn_tanh_kernel<HDIM><<<HID, 256>>>(pooled, lin1_w, lin1_b, g1, be1, c1, HID);
    lin_bn_tanh_kernel<HID><<<HID / 2, 256>>>(c1, lin2_w, lin2_b, g2, be2, c2, HID / 2);
    lin_bn_tanh_kernel<HID / 2><<<HID / 4, 256>>>(c2, lin3_w, lin3_b, g3, be3, c3, HID / 4);
    lin_final_kernel<<<10, 256>>>(c3, lin4_w, lin4_b, out);
}